// round 3
// baseline (speedup 1.0000x reference)
#include <cuda_runtime.h>
#include <math.h>

#define NN   10000
#define NE   320000
#define NF   512
#define NH1  32
#define NH2  16

// ---------------- scratch (allocation-free) ----------------
__device__ __align__(16) float g_xw0[NN * NH1];   // X @ W0
__device__ __align__(16) float g_h1 [NN * NH1];   // spmm accumulator -> relu'd on read
__device__ __align__(16) float g_hm [NN * NH2];   // relu(h1) @ W_mean
__device__ __align__(16) float g_hs [NN * NH2];   // relu(h1) @ W_std
__device__ __align__(16) float g_zm [NN * NH2];   // spmm accumulator (mean)
__device__ __align__(16) float g_zs [NN * NH2];   // spmm accumulator (log_std)
__device__ __align__(16) float g_z  [NN * NH2];   // z = zm + eps*exp(zs)

// ---------------- K0: zero accumulators (every launch; replays deterministic)
__global__ void zero_kernel() {
    int t = blockIdx.x * blockDim.x + threadIdx.x;
    if (t < NN * NH1) g_h1[t] = 0.f;
    if (t < NN * NH2) { g_zm[t] = 0.f; g_zs[t] = 0.f; }
}

// ---------------- K1: XW0 = features @ W0   [10000x512]@[512x32]
// block=256 threads covers 128 rows; thread = 4 rows x 4 cols
__global__ void xw0_kernel(const float* __restrict__ x, const float* __restrict__ W0) {
    int tid = threadIdx.x;
    int c4 = (tid & 7) * 4;
    int r0 = blockIdx.x * 128 + (tid >> 3) * 4;
    float acc[4][4];
#pragma unroll
    for (int r = 0; r < 4; r++)
#pragma unroll
        for (int c = 0; c < 4; c++) acc[r][c] = 0.f;

    const float* xp = x + (long long)r0 * NF;
    if (r0 + 4 <= NN) {
#pragma unroll 8
        for (int k = 0; k < NF; k++) {
            float4 w = *(const float4*)(W0 + k * NH1 + c4);
#pragma unroll
            for (int r = 0; r < 4; r++) {
                float xv = xp[r * NF + k];
                acc[r][0] += xv * w.x; acc[r][1] += xv * w.y;
                acc[r][2] += xv * w.z; acc[r][3] += xv * w.w;
            }
        }
#pragma unroll
        for (int r = 0; r < 4; r++)
            *(float4*)(&g_xw0[(r0 + r) * NH1 + c4]) =
                make_float4(acc[r][0], acc[r][1], acc[r][2], acc[r][3]);
    } else {
        for (int k = 0; k < NF; k++) {
            float4 w = *(const float4*)(W0 + k * NH1 + c4);
            for (int r = 0; r < 4; r++) {
                if (r0 + r < NN) {
                    float xv = xp[r * NF + k];
                    acc[r][0] += xv * w.x; acc[r][1] += xv * w.y;
                    acc[r][2] += xv * w.z; acc[r][3] += xv * w.w;
                }
            }
        }
        for (int r = 0; r < 4; r++)
            if (r0 + r < NN)
                *(float4*)(&g_xw0[(r0 + r) * NH1 + c4]) =
                    make_float4(acc[r][0], acc[r][1], acc[r][2], acc[r][3]);
    }
}

// ---------------- K2: spmm layer 1: h1[dst] += w * xw0[src], D=32
// thread = (edge, 4-col chunk); 8 chunks per edge; scalar atomicAdd (vanilla)
__global__ void spmm1_kernel(const int* __restrict__ ei, const float* __restrict__ ew) {
    int t = blockIdx.x * blockDim.x + threadIdx.x;
    int e = t >> 3;
    if (e >= NE) return;
    int q = (t & 7) * 4;
    int s = ei[e];
    int d = ei[NE + e];
    float w = ew[e];
    float4 v = *(const float4*)(g_xw0 + s * NH1 + q);
    float* dst = g_h1 + d * NH1 + q;
    atomicAdd(dst + 0, w * v.x);
    atomicAdd(dst + 1, w * v.y);
    atomicAdd(dst + 2, w * v.z);
    atomicAdd(dst + 3, w * v.w);
}

// ---------------- K3: hm = relu(h1) @ W_mean ; hs = relu(h1) @ W_std
__global__ void heads_kernel(const float* __restrict__ Wm, const float* __restrict__ Ws) {
    int t = blockIdx.x * blockDim.x + threadIdx.x;
    if (t >= NN * NH2 * 2) return;
    int i = t >> 5;
    int rr = t & 31;
    int j = rr & 15;
    const float* W = (rr < 16) ? Wm : Ws;
    float*     dst = (rr < 16) ? g_hm : g_hs;
    float acc = 0.f;
#pragma unroll
    for (int c = 0; c < NH1; c++)
        acc += fmaxf(g_h1[i * NH1 + c], 0.f) * W[c * NH2 + j];
    dst[i * NH2 + j] = acc;
}

// ---------------- K4: spmm layer 2 (both heads), D=16 each
__global__ void spmm2_kernel(const int* __restrict__ ei, const float* __restrict__ ew) {
    int t = blockIdx.x * blockDim.x + threadIdx.x;
    int e = t >> 3;
    if (e >= NE) return;
    int qq = t & 7;
    int q = (qq & 3) * 4;
    int s = ei[e];
    int d = ei[NE + e];
    float w = ew[e];
    const float* sb = (qq < 4) ? g_hm : g_hs;
    float*       db = (qq < 4) ? g_zm : g_zs;
    float4 v = *(const float4*)(sb + s * NH2 + q);
    float* dst = db + d * NH2 + q;
    atomicAdd(dst + 0, w * v.x);
    atomicAdd(dst + 1, w * v.y);
    atomicAdd(dst + 2, w * v.z);
    atomicAdd(dst + 3, w * v.w);
}

// ---------------- K5: z = zm + eps*exp(zs); optionally emit zm/zs outputs
__global__ void z_kernel(const float* __restrict__ eps,
                         float* __restrict__ out_zm, float* __restrict__ out_zs) {
    int t = blockIdx.x * blockDim.x + threadIdx.x;
    if (t >= NN * NH2) return;
    float zm = g_zm[t];
    float zs = g_zs[t];
    g_z[t] = zm + eps[t] * expf(zs);
    if (out_zm) { out_zm[t] = zm; out_zs[t] = zs; }
}

// ---------------- K6: recon = z @ z.T  (10000x10000 fp32, 400MB store)
// 128x128 tile per CTA, 8x8 per thread, plain FFMA accumulation
__global__ __launch_bounds__(256) void recon_kernel(float* __restrict__ out) {
    __shared__ float zi[16][132];   // transposed: zi[k][row]
    __shared__ float zj[16][132];
    int t  = threadIdx.x;
    int i0 = blockIdx.y * 128;
    int j0 = blockIdx.x * 128;

#pragma unroll
    for (int it = 0; it < 8; it++) {
        int idx = t + it * 256;           // 0..2047
        int r = idx >> 4, c = idx & 15;
        zi[c][r] = (i0 + r < NN) ? g_z[(i0 + r) * NH2 + c] : 0.f;
        zj[c][r] = (j0 + r < NN) ? g_z[(j0 + r) * NH2 + c] : 0.f;
    }
    __syncthreads();

    int tx = t & 15, ty = t >> 4;
    float acc[8][8];
#pragma unroll
    for (int r = 0; r < 8; r++)
#pragma unroll
        for (int c = 0; c < 8; c++) acc[r][c] = 0.f;

#pragma unroll
    for (int k = 0; k < 16; k++) {
        float4 a0 = *(const float4*)&zi[k][ty * 8];
        float4 a1 = *(const float4*)&zi[k][ty * 8 + 4];
        float4 b0 = *(const float4*)&zj[k][tx * 8];
        float4 b1 = *(const float4*)&zj[k][tx * 8 + 4];
        float av[8] = {a0.x, a0.y, a0.z, a0.w, a1.x, a1.y, a1.z, a1.w};
        float bv[8] = {b0.x, b0.y, b0.z, b0.w, b1.x, b1.y, b1.z, b1.w};
#pragma unroll
        for (int r = 0; r < 8; r++)
#pragma unroll
            for (int c = 0; c < 8; c++)
                acc[r][c] += av[r] * bv[c];
    }

    int col = j0 + tx * 8;
    bool colok = (col + 7 < NN);          // NN % 8 == 0 -> all-or-nothing
#pragma unroll
    for (int r = 0; r < 8; r++) {
        int row = i0 + ty * 8 + r;
        if (row < NN && colok) {
            float4* p = (float4*)(out + (long long)row * NN + col);
            p[0] = make_float4(acc[r][0], acc[r][1], acc[r][2], acc[r][3]);
            p[1] = make_float4(acc[r][4], acc[r][5], acc[r][6], acc[r][7]);
        }
    }
}

// ---------------- launch ----------------
extern "C" void kernel_launch(void* const* d_in, const int* in_sizes, int n_in,
                              void* d_out, int out_size) {
    const float* features = (const float*)d_in[0];
    const int*   ei       = (const int*)  d_in[1];   // [2,E]: src then dst
    const float* ew       = (const float*)d_in[2];
    const float* eps      = (const float*)d_in[3];
    const float* W0       = (const float*)d_in[4];
    const float* Wm       = (const float*)d_in[5];
    const float* Ws       = (const float*)d_in[6];
    float* out = (float*)d_out;

    zero_kernel <<<1250, 256>>>();
    xw0_kernel  <<<(NN + 127) / 128, 256>>>(features, W0);
    spmm1_kernel<<<(NE * 8 + 255) / 256, 256>>>(ei, ew);
    heads_kernel<<<(NN * NH2 * 2 + 255) / 256, 256>>>(Wm, Ws);
    spmm2_kernel<<<(NE * 8 + 255) / 256, 256>>>(ei, ew);

    long long need = (long long)NN * NN + 2LL * NN * NH2;
    bool tail = ((long long)out_size >= need);
    float* ozm = tail ? out + (long long)NN * NN : nullptr;
    float* ozs = tail ? out + (long long)NN * NN + NN * NH2 : nullptr;
    z_kernel<<<(NN * NH2 + 255) / 256, 256>>>(eps, ozm, ozs);

    dim3 grid((NN + 127) / 128, (NN + 127) / 128);
    recon_kernel<<<grid, 256>>>(out);
}

// round 4
// speedup vs baseline: 1.0876x; 1.0876x over previous
#include <cuda_runtime.h>
#include <math.h>

#define NN   10000
#define NE   320000
#define NF   512
#define NH1  32
#define NH2  16

// ---------------- scratch (allocation-free, 16B aligned for v4 ops) ----------------
__device__ __align__(16) float g_xw0[NN * NH1];   // X @ W0
__device__ __align__(16) float g_h1 [NN * NH1];   // spmm accumulator -> relu'd on read
__device__ __align__(16) float g_hm [NN * NH2];   // relu(h1) @ W_mean
__device__ __align__(16) float g_hs [NN * NH2];   // relu(h1) @ W_std
__device__ __align__(16) float g_zm [NN * NH2];   // spmm accumulator (mean)
__device__ __align__(16) float g_zs [NN * NH2];   // spmm accumulator (log_std)
__device__ __align__(16) float g_z  [NN * NH2];   // z = zm + eps*exp(zs)

// ---------------- asm helpers ----------------
__device__ __forceinline__ void red_add_v4(float* addr, float a, float b, float c, float d) {
    asm volatile("red.global.add.v4.f32 [%0], {%1, %2, %3, %4};"
                 :: "l"(addr), "f"(a), "f"(b), "f"(c), "f"(d) : "memory");
}
__device__ __forceinline__ unsigned long long pk(float lo, float hi) {
    unsigned long long r;
    asm("mov.b64 %0, {%1, %2};" : "=l"(r) : "f"(lo), "f"(hi));
    return r;
}
__device__ __forceinline__ void upk(unsigned long long v, float& lo, float& hi) {
    asm("mov.b64 {%0, %1}, %2;" : "=f"(lo), "=f"(hi) : "l"(v));
}
__device__ __forceinline__ void fma2(unsigned long long& d, unsigned long long a, unsigned long long b) {
    asm("fma.rn.f32x2 %0, %1, %2, %0;" : "+l"(d) : "l"(a), "l"(b));
}

// ---------------- K0: zero accumulators (every launch; replays deterministic)
__global__ void zero_kernel() {
    int t = blockIdx.x * blockDim.x + threadIdx.x;
    if (t < NN * NH1) g_h1[t] = 0.f;
    if (t < NN * NH2) { g_zm[t] = 0.f; g_zs[t] = 0.f; }
}

// ---------------- K1: XW0 = features @ W0   [10000x512]@[512x32]
__global__ void xw0_kernel(const float* __restrict__ x, const float* __restrict__ W0) {
    int tid = threadIdx.x;
    int c4 = (tid & 7) * 4;
    int r0 = blockIdx.x * 128 + (tid >> 3) * 4;
    float acc[4][4];
#pragma unroll
    for (int r = 0; r < 4; r++)
#pragma unroll
        for (int c = 0; c < 4; c++) acc[r][c] = 0.f;

    const float* xp = x + (long long)r0 * NF;
    if (r0 + 4 <= NN) {
#pragma unroll 8
        for (int k = 0; k < NF; k++) {
            float4 w = *(const float4*)(W0 + k * NH1 + c4);
#pragma unroll
            for (int r = 0; r < 4; r++) {
                float xv = __ldg(xp + r * NF + k);
                acc[r][0] += xv * w.x; acc[r][1] += xv * w.y;
                acc[r][2] += xv * w.z; acc[r][3] += xv * w.w;
            }
        }
#pragma unroll
        for (int r = 0; r < 4; r++)
            *(float4*)(&g_xw0[(r0 + r) * NH1 + c4]) =
                make_float4(acc[r][0], acc[r][1], acc[r][2], acc[r][3]);
    } else {
        for (int k = 0; k < NF; k++) {
            float4 w = *(const float4*)(W0 + k * NH1 + c4);
            for (int r = 0; r < 4; r++) {
                if (r0 + r < NN) {
                    float xv = __ldg(xp + r * NF + k);
                    acc[r][0] += xv * w.x; acc[r][1] += xv * w.y;
                    acc[r][2] += xv * w.z; acc[r][3] += xv * w.w;
                }
            }
        }
        for (int r = 0; r < 4; r++)
            if (r0 + r < NN)
                *(float4*)(&g_xw0[(r0 + r) * NH1 + c4]) =
                    make_float4(acc[r][0], acc[r][1], acc[r][2], acc[r][3]);
    }
}

// ---------------- K2: spmm layer 1: h1[dst] += w * xw0[src], D=32
// thread = (edge, 4-col chunk); vectorized global reduction
__global__ void spmm1_kernel(const int* __restrict__ ei, const float* __restrict__ ew) {
    int t = blockIdx.x * blockDim.x + threadIdx.x;
    int e = t >> 3;
    if (e >= NE) return;
    int q = (t & 7) * 4;
    int s = __ldg(ei + e);
    int d = __ldg(ei + NE + e);
    float w = __ldg(ew + e);
    float4 v = *(const float4*)(g_xw0 + s * NH1 + q);
    red_add_v4(g_h1 + d * NH1 + q, w * v.x, w * v.y, w * v.z, w * v.w);
}

// ---------------- K3: hm = relu(h1) @ W_mean ; hs = relu(h1) @ W_std
__global__ void heads_kernel(const float* __restrict__ Wm, const float* __restrict__ Ws) {
    int t = blockIdx.x * blockDim.x + threadIdx.x;
    if (t >= NN * NH2 * 2) return;
    int i = t >> 5;
    int rr = t & 31;
    int j = rr & 15;
    const float* W = (rr < 16) ? Wm : Ws;
    float*     dst = (rr < 16) ? g_hm : g_hs;
    float acc = 0.f;
#pragma unroll
    for (int c = 0; c < NH1; c++)
        acc += fmaxf(g_h1[i * NH1 + c], 0.f) * W[c * NH2 + j];
    dst[i * NH2 + j] = acc;
}

// ---------------- K4: spmm layer 2 (both heads), D=16 each
__global__ void spmm2_kernel(const int* __restrict__ ei, const float* __restrict__ ew) {
    int t = blockIdx.x * blockDim.x + threadIdx.x;
    int e = t >> 3;
    if (e >= NE) return;
    int qq = t & 7;
    int q = (qq & 3) * 4;
    int s = __ldg(ei + e);
    int d = __ldg(ei + NE + e);
    float w = __ldg(ew + e);
    const float* sb = (qq < 4) ? g_hm : g_hs;
    float*       db = (qq < 4) ? g_zm : g_zs;
    float4 v = *(const float4*)(sb + s * NH2 + q);
    red_add_v4(db + d * NH2 + q, w * v.x, w * v.y, w * v.z, w * v.w);
}

// ---------------- K5: z = zm + eps*exp(zs); optionally emit zm/zs outputs
__global__ void z_kernel(const float* __restrict__ eps,
                         float* __restrict__ out_zm, float* __restrict__ out_zs) {
    int t = blockIdx.x * blockDim.x + threadIdx.x;
    if (t >= NN * NH2) return;
    float zm = g_zm[t];
    float zs = g_zs[t];
    g_z[t] = zm + eps[t] * expf(zs);
    if (out_zm) { out_zm[t] = zm; out_zs[t] = zs; }
}

// ---------------- K6: recon = z @ z.T  (10000x10000 fp32, 400MB store)
// 128x128 tile per CTA, 8x8 per thread, packed fma.rn.f32x2 accumulation
__global__ __launch_bounds__(256) void recon_kernel(float* __restrict__ out) {
    __shared__ float zi[16][132];   // transposed: zi[k][row]
    __shared__ float zj[16][132];
    int t  = threadIdx.x;
    int i0 = blockIdx.y * 128;
    int j0 = blockIdx.x * 128;

#pragma unroll
    for (int it = 0; it < 8; it++) {
        int idx = t + it * 256;           // 0..2047
        int r = idx >> 4, c = idx & 15;
        zi[c][r] = (i0 + r < NN) ? g_z[(i0 + r) * NH2 + c] : 0.f;
        zj[c][r] = (j0 + r < NN) ? g_z[(j0 + r) * NH2 + c] : 0.f;
    }
    __syncthreads();

    int tx = t & 15, ty = t >> 4;
    unsigned long long acc[8][4];
#pragma unroll
    for (int r = 0; r < 8; r++)
#pragma unroll
        for (int c = 0; c < 4; c++) acc[r][c] = 0ull;   // {0.f, 0.f}

#pragma unroll
    for (int k = 0; k < 16; k++) {
        float4 a0 = *(const float4*)&zi[k][ty * 8];
        float4 a1 = *(const float4*)&zi[k][ty * 8 + 4];
        float4 b0 = *(const float4*)&zj[k][tx * 8];
        float4 b1 = *(const float4*)&zj[k][tx * 8 + 4];
        unsigned long long bb0 = pk(b0.x, b0.y), bb1 = pk(b0.z, b0.w);
        unsigned long long bb2 = pk(b1.x, b1.y), bb3 = pk(b1.z, b1.w);
        float av[8] = {a0.x, a0.y, a0.z, a0.w, a1.x, a1.y, a1.z, a1.w};
#pragma unroll
        for (int r = 0; r < 8; r++) {
            unsigned long long aa = pk(av[r], av[r]);
            fma2(acc[r][0], aa, bb0);
            fma2(acc[r][1], aa, bb1);
            fma2(acc[r][2], aa, bb2);
            fma2(acc[r][3], aa, bb3);
        }
    }

    int col = j0 + tx * 8;
    bool colok = (col + 7 < NN);          // NN % 8 == 0 -> all-or-nothing
#pragma unroll
    for (int r = 0; r < 8; r++) {
        int row = i0 + ty * 8 + r;
        if (row < NN && colok) {
            float o[8];
            upk(acc[r][0], o[0], o[1]);
            upk(acc[r][1], o[2], o[3]);
            upk(acc[r][2], o[4], o[5]);
            upk(acc[r][3], o[6], o[7]);
            float4* p = (float4*)(out + (long long)row * NN + col);
            p[0] = make_float4(o[0], o[1], o[2], o[3]);
            p[1] = make_float4(o[4], o[5], o[6], o[7]);
        }
    }
}

// ---------------- launch ----------------
extern "C" void kernel_launch(void* const* d_in, const int* in_sizes, int n_in,
                              void* d_out, int out_size) {
    const float* features = (const float*)d_in[0];
    const int*   ei       = (const int*)  d_in[1];   // [2,E]: src then dst
    const float* ew       = (const float*)d_in[2];
    const float* eps      = (const float*)d_in[3];
    const float* W0       = (const float*)d_in[4];
    const float* Wm       = (const float*)d_in[5];
    const float* Ws       = (const float*)d_in[6];
    float* out = (float*)d_out;

    zero_kernel <<<1250, 256>>>();
    xw0_kernel  <<<(NN + 127) / 128, 256>>>(features, W0);
    spmm1_kernel<<<(NE * 8 + 255) / 256, 256>>>(ei, ew);
    heads_kernel<<<(NN * NH2 * 2 + 255) / 256, 256>>>(Wm, Ws);
    spmm2_kernel<<<(NE * 8 + 255) / 256, 256>>>(ei, ew);

    long long need = (long long)NN * NN + 2LL * NN * NH2;
    bool tail = ((long long)out_size >= need);
    float* ozm = tail ? out + (long long)NN * NN : nullptr;
    float* ozs = tail ? out + (long long)NN * NN + NN * NH2 : nullptr;
    z_kernel<<<(NN * NH2 + 255) / 256, 256>>>(eps, ozm, ozs);

    dim3 grid((NN + 127) / 128, (NN + 127) / 128);
    recon_kernel<<<grid, 256>>>(out);
}